// round 3
// baseline (speedup 1.0000x reference)
#include <cuda_runtime.h>

#define NN 20000      // nodes
#define NE 160000     // edges
#define TE 320000     // 2E edge-rows
#define HH 128

// ---------------- scratch (static __device__, no allocs) ----------------
__device__ __align__(128) float s_a0  [(size_t)NN * 128];   // nr @ W0
__device__ __align__(128) float s_a1  [(size_t)NN * 128];   // nr @ W1
__device__ __align__(128) float s_pre1[(size_t)TE * 128];   // lvl1 pre-act
__device__ __align__(128) float s_nacc[(size_t)NN * 128];   // node scatter accum
__device__ __align__(128) float s_nin [(size_t)NN * 128];
__device__ __align__(128) float s_np1 [(size_t)NN * 256];   // raw pre-act
__device__ __align__(128) float s_np2 [(size_t)NN * 128];   // raw pre-act
__device__ __align__(128) float s_ep1 [(size_t)TE * 256];   // raw pre-act
__device__ __align__(128) float s_ep2 [(size_t)TE * 128];   // raw pre-act
__device__ float s_sum[5 * 256];
__device__ float s_sq [5 * 256];
__device__ int   s_u[NE];
__device__ int   s_v[NE];
__device__ int   g_is64;

// ---------------- helpers ----------------
__global__ void k_zero() {
    size_t stride = (size_t)gridDim.x * blockDim.x;
    size_t i0 = (size_t)blockIdx.x * blockDim.x + threadIdx.x;
    size_t n = (size_t)NN * 128;
    for (size_t i = i0; i < n; i += stride) s_nacc[i] = 0.0f;
    if (i0 < 5 * 256) { s_sum[i0] = 0.0f; s_sq[i0] = 0.0f; }
}

// edge_index may be int64 (high words all 0) or int32. Detect.
__global__ void k_detect(const int* __restrict__ ei32) {
    if (threadIdx.x == 0 && blockIdx.x == 0) {
        int nz = 0;
        for (int i = 0; i < 256; i++) nz |= ei32[2 * i + 1];
        g_is64 = (nz == 0) ? 1 : 0;
    }
}

__global__ void k_decode(const void* __restrict__ ei) {
    int e = blockIdx.x * blockDim.x + threadIdx.x;
    if (e >= NE) return;
    if (g_is64) {
        const long long* p = (const long long*)ei;
        s_u[e] = (int)p[e];
        s_v[e] = (int)p[NE + e];
    } else {
        const int* p = (const int*)ei;
        s_u[e] = p[e];
        s_v[e] = p[NE + e];
    }
}

__device__ __forceinline__ unsigned f2tf(float x) {
    unsigned r;
    asm("cvt.rna.tf32.f32 %0, %1;" : "=r"(r) : "f"(x));
    return r;
}

#define MMA_TF32(d, Af, Bf)                                                     \
    asm volatile(                                                               \
        "mma.sync.aligned.m16n8k8.row.col.f32.tf32.tf32.f32 "                   \
        "{%0,%1,%2,%3},{%4,%5,%6,%7},{%8,%9},{%0,%1,%2,%3};"                    \
        : "+f"(d[0]), "+f"(d[1]), "+f"(d[2]), "+f"(d[3])                        \
        : "r"(Af[0]), "r"(Af[1]), "r"(Af[2]), "r"(Af[3]),                       \
          "r"(Bf[0]), "r"(Bf[1]))

// shared MMA core macro bits (tile 128x128, BK=32, 8 warps 2x4, 64x32 per warp)

// ---------------- generic TF32 GEMM (same as R2) ----------------
__global__ __launch_bounds__(256, 2) void k_mma(
    const float* __restrict__ A, const float* __restrict__ Bm,
    float* __restrict__ C, int M, int K, int NC,
    float* __restrict__ sumO, float* __restrict__ sqO,
    const float* __restrict__ aSum, const float* __restrict__ aSq,
    const float* __restrict__ aG, const float* __restrict__ aBt, float aInv)
{
    __shared__ unsigned As[128][36];
    __shared__ unsigned Bs[32][136];
    __shared__ float scA[256], shA[256];

    const int tid = threadIdx.x;
    const int lane = tid & 31, warp = tid >> 5;
    const int group = lane >> 2, qt = lane & 3;
    const int warpM = warp & 1, warpN = warp >> 1;
    const int mBase = blockIdx.x * 128, nBase = blockIdx.y * 128;

    if (aG) {
        for (int k = tid; k < K; k += 256) {
            float mean = aSum[k] * aInv;
            float var  = aSq[k] * aInv - mean * mean;
            float s = aG[k] * rsqrtf(var + 1e-5f);
            scA[k] = s; shA[k] = aBt[k] - mean * s;
        }
        __syncthreads();
    }

    float acc[4][4][4];
#pragma unroll
    for (int mt = 0; mt < 4; mt++)
#pragma unroll
        for (int nt = 0; nt < 4; nt++)
#pragma unroll
            for (int i = 0; i < 4; i++) acc[mt][nt][i] = 0.0f;

    for (int k0 = 0; k0 < K; k0 += 32) {
#pragma unroll
        for (int it = 0; it < 4; it++) {
            int idx = tid + (it << 8);
            int row = idx >> 3, kq = (idx & 7) << 2;
            int gm = mBase + row, gk = k0 + kq;
            float4 v = make_float4(0.f, 0.f, 0.f, 0.f);
            if (gm < M) {
                v = *(const float4*)(A + (size_t)gm * K + gk);
                if (aG) {
                    v.x = fmaxf(fmaf(v.x, scA[gk + 0], shA[gk + 0]), 0.f);
                    v.y = fmaxf(fmaf(v.y, scA[gk + 1], shA[gk + 1]), 0.f);
                    v.z = fmaxf(fmaf(v.z, scA[gk + 2], shA[gk + 2]), 0.f);
                    v.w = fmaxf(fmaf(v.w, scA[gk + 3], shA[gk + 3]), 0.f);
                }
            }
            uint4 u;
            u.x = f2tf(v.x); u.y = f2tf(v.y); u.z = f2tf(v.z); u.w = f2tf(v.w);
            *(uint4*)&As[row][kq] = u;
        }
#pragma unroll
        for (int it = 0; it < 4; it++) {
            int idx = tid + (it << 8);
            int kr = idx >> 5, nc = (idx & 31) << 2;
            float4 v = *(const float4*)(Bm + (size_t)(k0 + kr) * NC + nBase + nc);
            uint4 u;
            u.x = f2tf(v.x); u.y = f2tf(v.y); u.z = f2tf(v.z); u.w = f2tf(v.w);
            *(uint4*)&Bs[kr][nc] = u;
        }
        __syncthreads();
#pragma unroll
        for (int ks = 0; ks < 4; ks++) {
            unsigned af[4][4], bf[4][2];
            int kc = ks * 8 + qt;
#pragma unroll
            for (int mt = 0; mt < 4; mt++) {
                int r = warpM * 64 + mt * 16 + group;
                af[mt][0] = As[r][kc];
                af[mt][1] = As[r + 8][kc];
                af[mt][2] = As[r][kc + 4];
                af[mt][3] = As[r + 8][kc + 4];
            }
#pragma unroll
            for (int nt = 0; nt < 4; nt++) {
                int cb = warpN * 32 + nt * 8 + group;
                bf[nt][0] = Bs[kc][cb];
                bf[nt][1] = Bs[kc + 4][cb];
            }
#pragma unroll
            for (int mt = 0; mt < 4; mt++)
#pragma unroll
                for (int nt = 0; nt < 4; nt++)
                    MMA_TF32(acc[mt][nt], af[mt], bf[nt]);
        }
        __syncthreads();
    }

    float cs[4][2], cq[4][2];
#pragma unroll
    for (int nt = 0; nt < 4; nt++) { cs[nt][0] = cs[nt][1] = 0.f; cq[nt][0] = cq[nt][1] = 0.f; }
#pragma unroll
    for (int mt = 0; mt < 4; mt++) {
        int r0 = mBase + warpM * 64 + mt * 16 + group;
        int r1 = r0 + 8;
#pragma unroll
        for (int nt = 0; nt < 4; nt++) {
            float c0 = acc[mt][nt][0], c1 = acc[mt][nt][1];
            float c2 = acc[mt][nt][2], c3 = acc[mt][nt][3];
            int cc = nBase + warpN * 32 + nt * 8 + 2 * qt;
            if (r0 < M) {
                *(float2*)(C + (size_t)r0 * NC + cc) = make_float2(c0, c1);
                cs[nt][0] += c0; cs[nt][1] += c1;
                cq[nt][0] += c0 * c0; cq[nt][1] += c1 * c1;
            }
            if (r1 < M) {
                *(float2*)(C + (size_t)r1 * NC + cc) = make_float2(c2, c3);
                cs[nt][0] += c2; cs[nt][1] += c3;
                cq[nt][0] += c2 * c2; cq[nt][1] += c3 * c3;
            }
        }
    }
    if (sumO) {
#pragma unroll
        for (int off = 4; off < 32; off <<= 1) {
#pragma unroll
            for (int nt = 0; nt < 4; nt++) {
#pragma unroll
                for (int p = 0; p < 2; p++) {
                    cs[nt][p] += __shfl_xor_sync(0xffffffffu, cs[nt][p], off);
                    cq[nt][p] += __shfl_xor_sync(0xffffffffu, cq[nt][p], off);
                }
            }
        }
        if (group == 0) {
#pragma unroll
            for (int nt = 0; nt < 4; nt++) {
                int cc = nBase + warpN * 32 + nt * 8 + 2 * qt;
                atomicAdd(sumO + cc,     cs[nt][0]);
                atomicAdd(sumO + cc + 1, cs[nt][1]);
                atomicAdd(sqO  + cc,     cq[nt][0]);
                atomicAdd(sqO  + cc + 1, cq[nt][1]);
            }
        }
    }
}

// ---------------- ew2 GEMM fused with combine: pre1 = er@W2c + a0[u]+a0[v]+a1[atom] ----------------
// M=TE, K=128, NC=128 (gridDim = (2500,1)). Stats into slot 0.
__global__ __launch_bounds__(256, 2) void k_mma_pre1(
    const float* __restrict__ A, const float* __restrict__ Bm,
    float* __restrict__ C, float* __restrict__ sumO, float* __restrict__ sqO)
{
    __shared__ unsigned As[128][36];
    __shared__ unsigned Bs[32][136];

    const int tid = threadIdx.x;
    const int lane = tid & 31, warp = tid >> 5;
    const int group = lane >> 2, qt = lane & 3;
    const int warpM = warp & 1, warpN = warp >> 1;
    const int mBase = blockIdx.x * 128;
    const int K = 128, NC = 128;

    float acc[4][4][4];
#pragma unroll
    for (int mt = 0; mt < 4; mt++)
#pragma unroll
        for (int nt = 0; nt < 4; nt++)
#pragma unroll
            for (int i = 0; i < 4; i++) acc[mt][nt][i] = 0.0f;

    for (int k0 = 0; k0 < K; k0 += 32) {
#pragma unroll
        for (int it = 0; it < 4; it++) {
            int idx = tid + (it << 8);
            int row = idx >> 3, kq = (idx & 7) << 2;
            float4 v = *(const float4*)(A + (size_t)(mBase + row) * K + k0 + kq);
            uint4 u;
            u.x = f2tf(v.x); u.y = f2tf(v.y); u.z = f2tf(v.z); u.w = f2tf(v.w);
            *(uint4*)&As[row][kq] = u;
        }
#pragma unroll
        for (int it = 0; it < 4; it++) {
            int idx = tid + (it << 8);
            int kr = idx >> 5, nc = (idx & 31) << 2;
            float4 v = *(const float4*)(Bm + (size_t)(k0 + kr) * NC + nc);
            uint4 u;
            u.x = f2tf(v.x); u.y = f2tf(v.y); u.z = f2tf(v.z); u.w = f2tf(v.w);
            *(uint4*)&Bs[kr][nc] = u;
        }
        __syncthreads();
#pragma unroll
        for (int ks = 0; ks < 4; ks++) {
            unsigned af[4][4], bf[4][2];
            int kc = ks * 8 + qt;
#pragma unroll
            for (int mt = 0; mt < 4; mt++) {
                int r = warpM * 64 + mt * 16 + group;
                af[mt][0] = As[r][kc];
                af[mt][1] = As[r + 8][kc];
                af[mt][2] = As[r][kc + 4];
                af[mt][3] = As[r + 8][kc + 4];
            }
#pragma unroll
            for (int nt = 0; nt < 4; nt++) {
                int cb = warpN * 32 + nt * 8 + group;
                bf[nt][0] = Bs[kc][cb];
                bf[nt][1] = Bs[kc + 4][cb];
            }
#pragma unroll
            for (int mt = 0; mt < 4; mt++)
#pragma unroll
                for (int nt = 0; nt < 4; nt++)
                    MMA_TF32(acc[mt][nt], af[mt], bf[nt]);
        }
        __syncthreads();
    }

    // epilogue: add gathered node terms, write pre1, accumulate stats
    float cs[4][2], cq[4][2];
#pragma unroll
    for (int nt = 0; nt < 4; nt++) { cs[nt][0] = cs[nt][1] = 0.f; cq[nt][0] = cq[nt][1] = 0.f; }
#pragma unroll
    for (int mt = 0; mt < 4; mt++) {
        int r0 = mBase + warpM * 64 + mt * 16 + group;
        int r1 = r0 + 8;
        int e0 = r0 >> 1, e1 = r1 >> 1;
        int u0 = s_u[e0], v0 = s_v[e0];
        int u1 = s_u[e1], v1 = s_v[e1];
        int x0 = (r0 & 1) ? v0 : u0;
        int x1 = (r1 & 1) ? v1 : u1;
        const float* b0u = s_a0 + (size_t)u0 * 128;
        const float* b0v = s_a0 + (size_t)v0 * 128;
        const float* b0x = s_a1 + (size_t)x0 * 128;
        const float* b1u = s_a0 + (size_t)u1 * 128;
        const float* b1v = s_a0 + (size_t)v1 * 128;
        const float* b1x = s_a1 + (size_t)x1 * 128;
#pragma unroll
        for (int nt = 0; nt < 4; nt++) {
            int cc = warpN * 32 + nt * 8 + 2 * qt;
            float2 ga = *(const float2*)(b0u + cc);
            float2 gb = *(const float2*)(b0v + cc);
            float2 gc = *(const float2*)(b0x + cc);
            float c0 = acc[mt][nt][0] + ga.x + gb.x + gc.x;
            float c1 = acc[mt][nt][1] + ga.y + gb.y + gc.y;
            *(float2*)(C + (size_t)r0 * NC + cc) = make_float2(c0, c1);
            cs[nt][0] += c0; cs[nt][1] += c1;
            cq[nt][0] += c0 * c0; cq[nt][1] += c1 * c1;

            float2 ha = *(const float2*)(b1u + cc);
            float2 hb = *(const float2*)(b1v + cc);
            float2 hc = *(const float2*)(b1x + cc);
            float c2 = acc[mt][nt][2] + ha.x + hb.x + hc.x;
            float c3 = acc[mt][nt][3] + ha.y + hb.y + hc.y;
            *(float2*)(C + (size_t)r1 * NC + cc) = make_float2(c2, c3);
            cs[nt][0] += c2; cs[nt][1] += c3;
            cq[nt][0] += c2 * c2; cq[nt][1] += c3 * c3;
        }
    }
#pragma unroll
    for (int off = 4; off < 32; off <<= 1) {
#pragma unroll
        for (int nt = 0; nt < 4; nt++) {
#pragma unroll
            for (int p = 0; p < 2; p++) {
                cs[nt][p] += __shfl_xor_sync(0xffffffffu, cs[nt][p], off);
                cq[nt][p] += __shfl_xor_sync(0xffffffffu, cq[nt][p], off);
            }
        }
    }
    if (group == 0) {
#pragma unroll
        for (int nt = 0; nt < 4; nt++) {
            int cc = warpN * 32 + nt * 8 + 2 * qt;
            atomicAdd(sumO + cc,     cs[nt][0]);
            atomicAdd(sumO + cc + 1, cs[nt][1]);
            atomicAdd(sqO  + cc,     cq[nt][0]);
            atomicAdd(sqO  + cc + 1, cq[nt][1]);
        }
    }
}

// ---------------- ep1 GEMM with edge_in built on the fly in the A loader ----------------
// A row gm (edge-row): cols 0..127 = fh(e) = (1+eps2)/2*(er0+er1)+nr[u]+nr[v]
//                      cols 128..255 = (1+eps2)*er[gm] + nr[atom]
// grid = dim3(2, 2500): nBase = bx*128, mBase = by*128 (adjacent blocks share A rows -> L2 reuse)
__global__ __launch_bounds__(256, 2) void k_mma_ein(
    const float* __restrict__ er, const float* __restrict__ nr,
    const float* __restrict__ Bm, float* __restrict__ C,
    float* __restrict__ sumO, float* __restrict__ sqO,
    const float* __restrict__ eps2p)
{
    __shared__ unsigned As[128][36];
    __shared__ unsigned Bs[32][136];

    const int tid = threadIdx.x;
    const int lane = tid & 31, warp = tid >> 5;
    const int group = lane >> 2, qt = lane & 3;
    const int warpM = warp & 1, warpN = warp >> 1;
    const int nBase = blockIdx.x * 128;
    const int mBase = blockIdx.y * 128;
    const int K = 256, NC = 256;
    const float e2 = 1.0f + *eps2p;
    const float e2h = 0.5f * e2;

    float acc[4][4][4];
#pragma unroll
    for (int mt = 0; mt < 4; mt++)
#pragma unroll
        for (int nt = 0; nt < 4; nt++)
#pragma unroll
            for (int i = 0; i < 4; i++) acc[mt][nt][i] = 0.0f;

    for (int k0 = 0; k0 < K; k0 += 32) {
        bool isFh = (k0 < 128);
#pragma unroll
        for (int it = 0; it < 4; it++) {
            int idx = tid + (it << 8);
            int row = idx >> 3, kq = (idx & 7) << 2;
            int gm = mBase + row;
            int e = gm >> 1;
            int u = s_u[e], vv = s_v[e];
            float4 v;
            if (isFh) {
                int c = k0 + kq;
                float4 a = *(const float4*)(er + (size_t)(2 * e) * 128 + c);
                float4 b = *(const float4*)(er + (size_t)(2 * e + 1) * 128 + c);
                float4 p = *(const float4*)(nr + (size_t)u * 128 + c);
                float4 q = *(const float4*)(nr + (size_t)vv * 128 + c);
                v.x = e2h * (a.x + b.x) + p.x + q.x;
                v.y = e2h * (a.y + b.y) + p.y + q.y;
                v.z = e2h * (a.z + b.z) + p.z + q.z;
                v.w = e2h * (a.w + b.w) + p.w + q.w;
            } else {
                int c = k0 - 128 + kq;
                int atom = (gm & 1) ? vv : u;
                float4 a = *(const float4*)(er + (size_t)gm * 128 + c);
                float4 p = *(const float4*)(nr + (size_t)atom * 128 + c);
                v.x = e2 * a.x + p.x;
                v.y = e2 * a.y + p.y;
                v.z = e2 * a.z + p.z;
                v.w = e2 * a.w + p.w;
            }
            uint4 u4;
            u4.x = f2tf(v.x); u4.y = f2tf(v.y); u4.z = f2tf(v.z); u4.w = f2tf(v.w);
            *(uint4*)&As[row][kq] = u4;
        }
#pragma unroll
        for (int it = 0; it < 4; it++) {
            int idx = tid + (it << 8);
            int kr = idx >> 5, nc = (idx & 31) << 2;
            float4 v = *(const float4*)(Bm + (size_t)(k0 + kr) * NC + nBase + nc);
            uint4 u4;
            u4.x = f2tf(v.x); u4.y = f2tf(v.y); u4.z = f2tf(v.z); u4.w = f2tf(v.w);
            *(uint4*)&Bs[kr][nc] = u4;
        }
        __syncthreads();
#pragma unroll
        for (int ks = 0; ks < 4; ks++) {
            unsigned af[4][4], bf[4][2];
            int kc = ks * 8 + qt;
#pragma unroll
            for (int mt = 0; mt < 4; mt++) {
                int r = warpM * 64 + mt * 16 + group;
                af[mt][0] = As[r][kc];
                af[mt][1] = As[r + 8][kc];
                af[mt][2] = As[r][kc + 4];
                af[mt][3] = As[r + 8][kc + 4];
            }
#pragma unroll
            for (int nt = 0; nt < 4; nt++) {
                int cb = warpN * 32 + nt * 8 + group;
                bf[nt][0] = Bs[kc][cb];
                bf[nt][1] = Bs[kc + 4][cb];
            }
#pragma unroll
            for (int mt = 0; mt < 4; mt++)
#pragma unroll
                for (int nt = 0; nt < 4; nt++)
                    MMA_TF32(acc[mt][nt], af[mt], bf[nt]);
        }
        __syncthreads();
    }

    float cs[4][2], cq[4][2];
#pragma unroll
    for (int nt = 0; nt < 4; nt++) { cs[nt][0] = cs[nt][1] = 0.f; cq[nt][0] = cq[nt][1] = 0.f; }
#pragma unroll
    for (int mt = 0; mt < 4; mt++) {
        int r0 = mBase + warpM * 64 + mt * 16 + group;
        int r1 = r0 + 8;
#pragma unroll
        for (int nt = 0; nt < 4; nt++) {
            float c0 = acc[mt][nt][0], c1 = acc[mt][nt][1];
            float c2 = acc[mt][nt][2], c3 = acc[mt][nt][3];
            int cc = nBase + warpN * 32 + nt * 8 + 2 * qt;
            *(float2*)(C + (size_t)r0 * NC + cc) = make_float2(c0, c1);
            *(float2*)(C + (size_t)r1 * NC + cc) = make_float2(c2, c3);
            cs[nt][0] += c0 + c2; cs[nt][1] += c1 + c3;
            cq[nt][0] += c0 * c0 + c2 * c2; cq[nt][1] += c1 * c1 + c3 * c3;
        }
    }
#pragma unroll
    for (int off = 4; off < 32; off <<= 1) {
#pragma unroll
        for (int nt = 0; nt < 4; nt++) {
#pragma unroll
            for (int p = 0; p < 2; p++) {
                cs[nt][p] += __shfl_xor_sync(0xffffffffu, cs[nt][p], off);
                cq[nt][p] += __shfl_xor_sync(0xffffffffu, cq[nt][p], off);
            }
        }
    }
    if (group == 0) {
#pragma unroll
        for (int nt = 0; nt < 4; nt++) {
            int cc = nBase + warpN * 32 + nt * 8 + 2 * qt;
            atomicAdd(sumO + cc,     cs[nt][0]);
            atomicAdd(sumO + cc + 1, cs[nt][1]);
            atomicAdd(sqO  + cc,     cq[nt][0]);
            atomicAdd(sqO  + cc + 1, cq[nt][1]);
        }
    }
}

// BN+ReLU on pre1, then scatter: nacc[u] += (1+eps12)*h0 + (h0+h1), sym for v
__global__ void k_scatter(const float* __restrict__ g, const float* __restrict__ b,
                          const float* __restrict__ eps12p) {
    int c = threadIdx.x;
    float mean = s_sum[c] * (1.0f / TE);
    float var  = s_sq[c]  * (1.0f / TE) - mean * mean;
    float sc = g[c] * rsqrtf(var + 1e-5f);
    float sh = b[c] - mean * sc;
    float e12 = 1.0f + *eps12p;
    for (int e = blockIdx.x; e < NE; e += gridDim.x) {
        int u = s_u[e], v = s_v[e];
        size_t r0 = (size_t)(2 * e) * 128, r1 = (size_t)(2 * e + 1) * 128;
        float h0 = fmaxf(s_pre1[r0 + c] * sc + sh, 0.f);
        float h1 = fmaxf(s_pre1[r1 + c] * sc + sh, 0.f);
        float ds = h0 + h1;
        atomicAdd(&s_nacc[(size_t)u * 128 + c], e12 * h0 + ds);
        atomicAdd(&s_nacc[(size_t)v * 128 + c], e12 * h1 + ds);
    }
}

__global__ void k_nin(const float* __restrict__ nr, const float* __restrict__ eps11p) {
    float e11 = 1.0f + *eps11p;
    size_t stride = (size_t)gridDim.x * blockDim.x;
    size_t n = (size_t)NN * 128;
    for (size_t i = (size_t)blockIdx.x * blockDim.x + threadIdx.x; i < n; i += stride)
        s_nin[i] = e11 * nr[i] + s_nacc[i];
}

// dst = relu(src*scale + shift)
__global__ void k_bnapply(const float* __restrict__ src, float* __restrict__ dst,
                          int rows, int colMask,
                          const float* __restrict__ sum, const float* __restrict__ sq,
                          const float* __restrict__ g, const float* __restrict__ b) {
    float inv = 1.0f / (float)rows;
    size_t n = (size_t)rows * (colMask + 1);
    size_t stride = (size_t)gridDim.x * blockDim.x;
    for (size_t i = (size_t)blockIdx.x * blockDim.x + threadIdx.x; i < n; i += stride) {
        int c = (int)(i & (size_t)colMask);
        float mean = sum[c] * inv;
        float var  = sq[c] * inv - mean * mean;
        float sc = g[c] * rsqrtf(var + 1e-5f);
        float v = src[i] * sc + (b[c] - mean * sc);
        dst[i] = fmaxf(v, 0.f);
    }
}

// ---------------- launch ----------------
extern "C" void kernel_launch(void* const* d_in, const int* in_sizes, int n_in,
                              void* d_out, int out_size) {
    const float* nr      = (const float*)d_in[0];
    const float* er      = (const float*)d_in[1];
    const void*  ei      = d_in[2];
    const float* lift_w1 = (const float*)d_in[3];
    const float* lift_g1 = (const float*)d_in[4];
    const float* lift_b1 = (const float*)d_in[5];
    const float* lift_w2 = (const float*)d_in[6];
    const float* lift_g2 = (const float*)d_in[7];
    const float* lift_b2 = (const float*)d_in[8];
    const float* lvl1_w  = (const float*)d_in[9];
    const float* lvl1_g  = (const float*)d_in[10];
    const float* lvl1_b  = (const float*)d_in[11];
    const float* lvl2_w1 = (const float*)d_in[12];
    const float* lvl2_g1 = (const float*)d_in[13];
    const float* lvl2_b1 = (const float*)d_in[14];
    const float* lvl2_w2 = (const float*)d_in[15];
    const float* lvl2_g2 = (const float*)d_in[16];
    const float* lvl2_b2 = (const float*)d_in[17];
    const float* eps11   = (const float*)d_in[18];
    const float* eps12   = (const float*)d_in[19];
    const float* eps2    = (const float*)d_in[20];

    float* out_node = (float*)d_out;
    float* out_edge = out_node + (size_t)NN * HH;

    float *p_a0, *p_a1, *p_pre1, *p_nin, *p_np1, *p_np2, *p_ep1, *p_ep2, *p_sum, *p_sq;
    cudaGetSymbolAddress((void**)&p_a0,  s_a0);
    cudaGetSymbolAddress((void**)&p_a1,  s_a1);
    cudaGetSymbolAddress((void**)&p_pre1, s_pre1);
    cudaGetSymbolAddress((void**)&p_nin, s_nin);
    cudaGetSymbolAddress((void**)&p_np1, s_np1);
    cudaGetSymbolAddress((void**)&p_np2, s_np2);
    cudaGetSymbolAddress((void**)&p_ep1, s_ep1);
    cudaGetSymbolAddress((void**)&p_ep2, s_ep2);
    cudaGetSymbolAddress((void**)&p_sum, s_sum);
    cudaGetSymbolAddress((void**)&p_sq,  s_sq);

    const int GN  = (NN + 127) / 128;  // 157
    const int GTE = TE / 128;          // 2500

    k_zero<<<2048, 256>>>();
    k_detect<<<1, 32>>>((const int*)ei);
    k_decode<<<(NE + 255) / 256, 256>>>(ei);

    // A0 = nr @ W[0:128], A1 = nr @ W[128:256]
    k_mma<<<dim3(GN, 1), 256>>>(nr, lvl1_w,             p_a0, NN, 128, 128,
                                nullptr, nullptr, nullptr, nullptr, nullptr, nullptr, 0.f);
    k_mma<<<dim3(GN, 1), 256>>>(nr, lvl1_w + 128 * 128, p_a1, NN, 128, 128,
                                nullptr, nullptr, nullptr, nullptr, nullptr, nullptr, 0.f);

    // pre1 = er @ W[256:384] + gathered node terms; stats slot 0
    k_mma_pre1<<<dim3(GTE, 1), 256>>>(er, lvl1_w + 256 * 128, p_pre1, p_sum, p_sq);
    k_scatter<<<2048, 128>>>(lvl1_g, lvl1_b, eps12);       // BN+ReLU + fused scatter

    // node path
    k_nin<<<4096, 256>>>(nr, eps11);
    k_mma<<<dim3(GN, 2), 256>>>(p_nin, lvl2_w1, p_np1, NN, 128, 256,
                                p_sum + 256, p_sq + 256,
                                nullptr, nullptr, nullptr, nullptr, 0.f);
    k_mma<<<dim3(GN, 1), 256>>>(p_np1, lvl2_w2, p_np2, NN, 256, 128,
                                p_sum + 512, p_sq + 512,
                                p_sum + 256, p_sq + 256, lvl2_g1, lvl2_b1, 1.0f / NN);
    k_bnapply<<<4096, 256>>>(p_np2, out_node, NN, 127, p_sum + 512, p_sq + 512, lvl2_g2, lvl2_b2);

    // edge path: ep1 built on the fly; stats slot 3 -> ep2 (BN fused on A) stats slot 4
    k_mma_ein<<<dim3(2, GTE), 256>>>(er, nr, lift_w1, p_ep1,
                                     p_sum + 768, p_sq + 768, eps2);
    k_mma<<<dim3(GTE, 1), 256>>>(p_ep1, lift_w2, p_ep2, TE, 256, 128,
                                 p_sum + 1024, p_sq + 1024,
                                 p_sum + 768, p_sq + 768, lift_g1, lift_b1, 1.0f / TE);
    k_bnapply<<<8192, 256>>>(p_ep2, out_edge, TE, 127, p_sum + 1024, p_sq + 1024, lift_g2, lift_b2);
}

// round 4
// speedup vs baseline: 1.5437x; 1.5437x over previous
#include <cuda_runtime.h>

#define NN 20000      // nodes
#define NE 160000     // edges
#define TE 320000     // 2E edge-rows
#define HH 128

// ---------------- scratch (static __device__, no allocs) ----------------
__device__ __align__(128) float s_ew2 [(size_t)TE * 128];   // er @ W2
__device__ __align__(128) float s_a0  [(size_t)NN * 128];   // nr @ W0
__device__ __align__(128) float s_a1  [(size_t)NN * 128];   // nr @ W1
__device__ __align__(128) float s_pre1[(size_t)TE * 128];   // lvl1 pre-act
__device__ __align__(128) float s_nacc[(size_t)NN * 128];   // node scatter accum
__device__ __align__(128) float s_nin [(size_t)NN * 128];
__device__ __align__(128) float s_np1 [(size_t)NN * 256];   // raw pre-act
__device__ __align__(128) float s_np2 [(size_t)NN * 128];   // raw pre-act
__device__ __align__(128) float s_ein [(size_t)TE * 256];
__device__ __align__(128) float s_ep1 [(size_t)TE * 256];   // raw pre-act
__device__ __align__(128) float s_ep2 [(size_t)TE * 128];   // raw pre-act
__device__ float s_sum[5 * 256];
__device__ float s_sq [5 * 256];
__device__ int   s_u[NE];
__device__ int   s_v[NE];
__device__ int   g_is64;

// ---------------- helpers ----------------
__global__ void k_zero() {
    size_t stride = (size_t)gridDim.x * blockDim.x;
    size_t i0 = (size_t)blockIdx.x * blockDim.x + threadIdx.x;
    size_t n = (size_t)NN * 128;
    for (size_t i = i0; i < n; i += stride) s_nacc[i] = 0.0f;
    if (i0 < 5 * 256) { s_sum[i0] = 0.0f; s_sq[i0] = 0.0f; }
}

__global__ void k_detect(const int* __restrict__ ei32) {
    if (threadIdx.x == 0 && blockIdx.x == 0) {
        int nz = 0;
        for (int i = 0; i < 256; i++) nz |= ei32[2 * i + 1];
        g_is64 = (nz == 0) ? 1 : 0;
    }
}

__global__ void k_decode(const void* __restrict__ ei) {
    int e = blockIdx.x * blockDim.x + threadIdx.x;
    if (e >= NE) return;
    if (g_is64) {
        const long long* p = (const long long*)ei;
        s_u[e] = (int)p[e];
        s_v[e] = (int)p[NE + e];
    } else {
        const int* p = (const int*)ei;
        s_u[e] = p[e];
        s_v[e] = p[NE + e];
    }
}

__device__ __forceinline__ unsigned f2tf(float x) {
    unsigned r;
    asm("cvt.rna.tf32.f32 %0, %1;" : "=r"(r) : "f"(x));
    return r;
}

__device__ __forceinline__ void cpasync16(void* smem_ptr, const void* gptr, int src_bytes) {
    unsigned saddr = (unsigned)__cvta_generic_to_shared(smem_ptr);
    asm volatile("cp.async.cg.shared.global [%0], [%1], 16, %2;"
                 :: "r"(saddr), "l"(gptr), "r"(src_bytes));
}
__device__ __forceinline__ void cpasync_commit() {
    asm volatile("cp.async.commit_group;");
}
template <int N>
__device__ __forceinline__ void cpasync_wait() {
    asm volatile("cp.async.wait_group %0;" :: "n"(N));
}

#define MMA_TF32(d, Af, Bf)                                                     \
    asm volatile(                                                               \
        "mma.sync.aligned.m16n8k8.row.col.f32.tf32.tf32.f32 "                   \
        "{%0,%1,%2,%3},{%4,%5,%6,%7},{%8,%9},{%0,%1,%2,%3};"                    \
        : "+f"(d[0]), "+f"(d[1]), "+f"(d[2]), "+f"(d[3])                        \
        : "r"(Af[0]), "r"(Af[1]), "r"(Af[2]), "r"(Af[3]),                       \
          "r"(Bf[0]), "r"(Bf[1]))

// ---------------- pipelined TF32 GEMM, 128x128 tile, BK=32, cp.async 2-stage ----------------
// C[M,NC] = bnrelu?(A)[M,K] @ B[K,NC]; optional BN stats of C to sumO/sqO.
// Dynamic smem: As[2][128*36] fp32 raw | Bs[2][32*136] fp32 raw | scS[256] | shS[256]
#define AS_STRIDE 36
#define BS_STRIDE 136
#define AS_TILE (128 * AS_STRIDE)
#define BS_TILE (32 * BS_STRIDE)
#define SMEM_FLOATS (2 * AS_TILE + 2 * BS_TILE + 512)
#define SMEM_BYTES (SMEM_FLOATS * 4)

template <bool FUSE_BN>
__global__ __launch_bounds__(256, 2) void k_mma_p(
    const float* __restrict__ A, const float* __restrict__ Bm,
    float* __restrict__ C, int M, int K, int NC,
    float* __restrict__ sumO, float* __restrict__ sqO,
    const float* __restrict__ aSum, const float* __restrict__ aSq,
    const float* __restrict__ aG, const float* __restrict__ aBt, float aInv)
{
    extern __shared__ float dsm[];
    float* AsB = dsm;
    float* BsB = dsm + 2 * AS_TILE;
    float* scS = dsm + 2 * AS_TILE + 2 * BS_TILE;
    float* shS = scS + 256;

    const int tid = threadIdx.x;
    const int lane = tid & 31, warp = tid >> 5;
    const int group = lane >> 2, qt = lane & 3;
    const int warpM = warp & 1, warpN = warp >> 1;
    const int mBase = blockIdx.x * 128, nBase = blockIdx.y * 128;
    const int nk = K >> 5;

    if (FUSE_BN) {
        if (tid < K) {
            float mean = aSum[tid] * aInv;
            float var  = aSq[tid] * aInv - mean * mean;
            float s = aG[tid] * rsqrtf(var + 1e-5f);
            scS[tid] = s; shS[tid] = aBt[tid] - mean * s;
        }
    }

    // per-thread load coords
    const int arow = tid >> 3, akq = (tid & 7) << 2;     // + it*32 rows
    const int bkr = tid >> 5, bnc = (tid & 31) << 2;     // + it*8 k-rows

    // issue tile i into buffer b
    auto issue = [&](int i, int b) {
        const int k0 = i << 5;
        float* As = AsB + b * AS_TILE;
        float* Bs = BsB + b * BS_TILE;
#pragma unroll
        for (int it = 0; it < 4; it++) {
            int row = arow + it * 32;
            int gm = mBase + row;
            const float* src = A + (size_t)(gm < M ? gm : 0) * K + k0 + akq;
            cpasync16(As + row * AS_STRIDE + akq, src, gm < M ? 16 : 0);
        }
#pragma unroll
        for (int it = 0; it < 4; it++) {
            int kr = bkr + it * 8;
            const float* src = Bm + (size_t)(k0 + kr) * NC + nBase + bnc;
            cpasync16(Bs + kr * BS_STRIDE + bnc, src, 16);
        }
        cpasync_commit();
    };

    float acc[4][4][4];
#pragma unroll
    for (int mt = 0; mt < 4; mt++)
#pragma unroll
        for (int nt = 0; nt < 4; nt++)
#pragma unroll
            for (int i = 0; i < 4; i++) acc[mt][nt][i] = 0.0f;

    issue(0, 0);

    for (int i = 0; i < nk; i++) {
        if (i + 1 < nk) { issue(i + 1, (i + 1) & 1); cpasync_wait<1>(); }
        else            { cpasync_wait<0>(); }
        __syncthreads();

        const float* As = AsB + (i & 1) * AS_TILE;
        const float* Bs = BsB + (i & 1) * BS_TILE;
        const int k0 = i << 5;
#pragma unroll
        for (int ks = 0; ks < 4; ks++) {
            const int kc = ks * 8 + qt;
            float sc0, sh0, sc1, sh1;
            if (FUSE_BN) {
                sc0 = scS[k0 + kc];     sh0 = shS[k0 + kc];
                sc1 = scS[k0 + kc + 4]; sh1 = shS[k0 + kc + 4];
            }
            unsigned af[4][4], bf[4][2];
#pragma unroll
            for (int mt = 0; mt < 4; mt++) {
                int r = warpM * 64 + mt * 16 + group;
                float a0 = As[r * AS_STRIDE + kc];
                float a1 = As[(r + 8) * AS_STRIDE + kc];
                float a2 = As[r * AS_STRIDE + kc + 4];
                float a3 = As[(r + 8) * AS_STRIDE + kc + 4];
                if (FUSE_BN) {
                    a0 = fmaxf(fmaf(a0, sc0, sh0), 0.f);
                    a1 = fmaxf(fmaf(a1, sc0, sh0), 0.f);
                    a2 = fmaxf(fmaf(a2, sc1, sh1), 0.f);
                    a3 = fmaxf(fmaf(a3, sc1, sh1), 0.f);
                }
                af[mt][0] = f2tf(a0); af[mt][1] = f2tf(a1);
                af[mt][2] = f2tf(a2); af[mt][3] = f2tf(a3);
            }
#pragma unroll
            for (int nt = 0; nt < 4; nt++) {
                int cb = warpN * 32 + nt * 8 + group;
                bf[nt][0] = f2tf(Bs[kc * BS_STRIDE + cb]);
                bf[nt][1] = f2tf(Bs[(kc + 4) * BS_STRIDE + cb]);
            }
#pragma unroll
            for (int mt = 0; mt < 4; mt++)
#pragma unroll
                for (int nt = 0; nt < 4; nt++)
                    MMA_TF32(acc[mt][nt], af[mt], bf[nt]);
        }
        __syncthreads();
    }

    // epilogue: store + per-thread column partials (guard OOB rows)
    float cs[4][2], cq[4][2];
#pragma unroll
    for (int nt = 0; nt < 4; nt++) { cs[nt][0] = cs[nt][1] = 0.f; cq[nt][0] = cq[nt][1] = 0.f; }
#pragma unroll
    for (int mt = 0; mt < 4; mt++) {
        int r0 = mBase + warpM * 64 + mt * 16 + group;
        int r1 = r0 + 8;
#pragma unroll
        for (int nt = 0; nt < 4; nt++) {
            float c0 = acc[mt][nt][0], c1 = acc[mt][nt][1];
            float c2 = acc[mt][nt][2], c3 = acc[mt][nt][3];
            int cc = nBase + warpN * 32 + nt * 8 + 2 * qt;
            if (r0 < M) {
                *(float2*)(C + (size_t)r0 * NC + cc) = make_float2(c0, c1);
                cs[nt][0] += c0; cs[nt][1] += c1;
                cq[nt][0] += c0 * c0; cq[nt][1] += c1 * c1;
            }
            if (r1 < M) {
                *(float2*)(C + (size_t)r1 * NC + cc) = make_float2(c2, c3);
                cs[nt][0] += c2; cs[nt][1] += c3;
                cq[nt][0] += c2 * c2; cq[nt][1] += c3 * c3;
            }
        }
    }
    if (sumO) {
#pragma unroll
        for (int off = 4; off < 32; off <<= 1) {
#pragma unroll
            for (int nt = 0; nt < 4; nt++) {
#pragma unroll
                for (int p = 0; p < 2; p++) {
                    cs[nt][p] += __shfl_xor_sync(0xffffffffu, cs[nt][p], off);
                    cq[nt][p] += __shfl_xor_sync(0xffffffffu, cq[nt][p], off);
                }
            }
        }
        if (group == 0) {
#pragma unroll
            for (int nt = 0; nt < 4; nt++) {
                int cc = nBase + warpN * 32 + nt * 8 + 2 * qt;
                atomicAdd(sumO + cc,     cs[nt][0]);
                atomicAdd(sumO + cc + 1, cs[nt][1]);
                atomicAdd(sqO  + cc,     cq[nt][0]);
                atomicAdd(sqO  + cc + 1, cq[nt][1]);
            }
        }
    }
}

// pre1[2e]   = A0[u]+A0[v]+A1[u]+EW2[2e]
// pre1[2e+1] = A0[u]+A0[v]+A1[v]+EW2[2e+1]; accumulate BN stats (slot 0)
__global__ void k_combine(const float* __restrict__ ew2) {
    int c = threadIdx.x;  // 128
    float ls = 0.f, lq = 0.f;
    for (int e = blockIdx.x; e < NE; e += gridDim.x) {
        int u = s_u[e], v = s_v[e];
        float a0u = s_a0[(size_t)u * 128 + c], a0v = s_a0[(size_t)v * 128 + c];
        float a1u = s_a1[(size_t)u * 128 + c], a1v = s_a1[(size_t)v * 128 + c];
        float base = a0u + a0v;
        size_t r0 = (size_t)(2 * e) * 128, r1 = (size_t)(2 * e + 1) * 128;
        float p0 = base + a1u + ew2[r0 + c];
        float p1 = base + a1v + ew2[r1 + c];
        s_pre1[r0 + c] = p0;
        s_pre1[r1 + c] = p1;
        ls += p0 + p1; lq += p0 * p0 + p1 * p1;
    }
    atomicAdd(&s_sum[c], ls);
    atomicAdd(&s_sq[c],  lq);
}

// BN+ReLU on pre1, then scatter: nacc[u] += (1+eps12)*h0 + (h0+h1), sym for v
__global__ void k_scatter(const float* __restrict__ g, const float* __restrict__ b,
                          const float* __restrict__ eps12p) {
    int c = threadIdx.x;
    float mean = s_sum[c] * (1.0f / TE);
    float var  = s_sq[c]  * (1.0f / TE) - mean * mean;
    float sc = g[c] * rsqrtf(var + 1e-5f);
    float sh = b[c] - mean * sc;
    float e12 = 1.0f + *eps12p;
    for (int e = blockIdx.x; e < NE; e += gridDim.x) {
        int u = s_u[e], v = s_v[e];
        size_t r0 = (size_t)(2 * e) * 128, r1 = (size_t)(2 * e + 1) * 128;
        float h0 = fmaxf(s_pre1[r0 + c] * sc + sh, 0.f);
        float h1 = fmaxf(s_pre1[r1 + c] * sc + sh, 0.f);
        float ds = h0 + h1;
        atomicAdd(&s_nacc[(size_t)u * 128 + c], e12 * h0 + ds);
        atomicAdd(&s_nacc[(size_t)v * 128 + c], e12 * h1 + ds);
    }
}

__global__ void k_nin(const float* __restrict__ nr, const float* __restrict__ eps11p) {
    float e11 = 1.0f + *eps11p;
    size_t stride = (size_t)gridDim.x * blockDim.x;
    size_t n = (size_t)NN * 128;
    for (size_t i = (size_t)blockIdx.x * blockDim.x + threadIdx.x; i < n; i += stride)
        s_nin[i] = e11 * nr[i] + s_nacc[i];
}

// edge_in rows: [fh(e), sh(r)]
__global__ void k_ein(const float* __restrict__ er, const float* __restrict__ nr,
                      const float* __restrict__ eps2p) {
    int c = threadIdx.x;
    float e2 = 1.0f + *eps2p;
    for (int e = blockIdx.x; e < NE; e += gridDim.x) {
        int u = s_u[e], v = s_v[e];
        size_t er0i = (size_t)(2 * e) * 128, er1i = (size_t)(2 * e + 1) * 128;
        float er0 = er[er0i + c], er1 = er[er1i + c];
        float nru = nr[(size_t)u * 128 + c], nrv = nr[(size_t)v * 128 + c];
        float fh = e2 * 0.5f * (er0 + er1) + nru + nrv;
        size_t r0 = (size_t)(2 * e) * 256, r1 = (size_t)(2 * e + 1) * 256;
        s_ein[r0 + c] = fh;
        s_ein[r1 + c] = fh;
        s_ein[r0 + 128 + c] = e2 * er0 + nru;
        s_ein[r1 + 128 + c] = e2 * er1 + nrv;
    }
}

// dst = relu(src*scale + shift)
__global__ void k_bnapply(const float* __restrict__ src, float* __restrict__ dst,
                          int rows, int colMask,
                          const float* __restrict__ sum, const float* __restrict__ sq,
                          const float* __restrict__ g, const float* __restrict__ b) {
    float inv = 1.0f / (float)rows;
    size_t n = (size_t)rows * (colMask + 1);
    size_t stride = (size_t)gridDim.x * blockDim.x;
    for (size_t i = (size_t)blockIdx.x * blockDim.x + threadIdx.x; i < n; i += stride) {
        int c = (int)(i & (size_t)colMask);
        float mean = sum[c] * inv;
        float var  = sq[c] * inv - mean * mean;
        float sc = g[c] * rsqrtf(var + 1e-5f);
        float v = src[i] * sc + (b[c] - mean * sc);
        dst[i] = fmaxf(v, 0.f);
    }
}

// ---------------- launch ----------------
extern "C" void kernel_launch(void* const* d_in, const int* in_sizes, int n_in,
                              void* d_out, int out_size) {
    const float* nr      = (const float*)d_in[0];
    const float* er      = (const float*)d_in[1];
    const void*  ei      = d_in[2];
    const float* lift_w1 = (const float*)d_in[3];
    const float* lift_g1 = (const float*)d_in[4];
    const float* lift_b1 = (const float*)d_in[5];
    const float* lift_w2 = (const float*)d_in[6];
    const float* lift_g2 = (const float*)d_in[7];
    const float* lift_b2 = (const float*)d_in[8];
    const float* lvl1_w  = (const float*)d_in[9];
    const float* lvl1_g  = (const float*)d_in[10];
    const float* lvl1_b  = (const float*)d_in[11];
    const float* lvl2_w1 = (const float*)d_in[12];
    const float* lvl2_g1 = (const float*)d_in[13];
    const float* lvl2_b1 = (const float*)d_in[14];
    const float* lvl2_w2 = (const float*)d_in[15];
    const float* lvl2_g2 = (const float*)d_in[16];
    const float* lvl2_b2 = (const float*)d_in[17];
    const float* eps11   = (const float*)d_in[18];
    const float* eps12   = (const float*)d_in[19];
    const float* eps2    = (const float*)d_in[20];

    float* out_node = (float*)d_out;
    float* out_edge = out_node + (size_t)NN * HH;

    float *p_ew2, *p_a0, *p_a1, *p_nin, *p_np1, *p_np2, *p_ein, *p_ep1, *p_ep2, *p_sum, *p_sq;
    cudaGetSymbolAddress((void**)&p_ew2, s_ew2);
    cudaGetSymbolAddress((void**)&p_a0,  s_a0);
    cudaGetSymbolAddress((void**)&p_a1,  s_a1);
    cudaGetSymbolAddress((void**)&p_nin, s_nin);
    cudaGetSymbolAddress((void**)&p_np1, s_np1);
    cudaGetSymbolAddress((void**)&p_np2, s_np2);
    cudaGetSymbolAddress((void**)&p_ein, s_ein);
    cudaGetSymbolAddress((void**)&p_ep1, s_ep1);
    cudaGetSymbolAddress((void**)&p_ep2, s_ep2);
    cudaGetSymbolAddress((void**)&p_sum, s_sum);
    cudaGetSymbolAddress((void**)&p_sq,  s_sq);

    static int smem_set = 0;
    if (!smem_set) {
        cudaFuncSetAttribute(k_mma_p<false>, cudaFuncAttributeMaxDynamicSharedMemorySize, SMEM_BYTES);
        cudaFuncSetAttribute(k_mma_p<true>,  cudaFuncAttributeMaxDynamicSharedMemorySize, SMEM_BYTES);
        smem_set = 1;
    }

    const int GN  = (NN + 127) / 128;  // 157
    const int GTE = TE / 128;          // 2500

    k_zero<<<2048, 256>>>();
    k_detect<<<1, 32>>>((const int*)ei);
    k_decode<<<(NE + 255) / 256, 256>>>(ei);

    // lvl1 pieces: EW2 = er @ W[256:384], A0 = nr @ W[0:128], A1 = nr @ W[128:256]
    k_mma_p<false><<<dim3(GTE, 1), 256, SMEM_BYTES>>>(er, lvl1_w + 256 * 128, p_ew2, TE, 128, 128,
                                 nullptr, nullptr, nullptr, nullptr, nullptr, nullptr, 0.f);
    k_mma_p<false><<<dim3(GN, 1), 256, SMEM_BYTES>>>(nr, lvl1_w,             p_a0, NN, 128, 128,
                                 nullptr, nullptr, nullptr, nullptr, nullptr, nullptr, 0.f);
    k_mma_p<false><<<dim3(GN, 1), 256, SMEM_BYTES>>>(nr, lvl1_w + 128 * 128, p_a1, NN, 128, 128,
                                 nullptr, nullptr, nullptr, nullptr, nullptr, nullptr, 0.f);

    k_combine<<<2048, 128>>>(p_ew2);                       // stats slot 0
    k_scatter<<<2048, 128>>>(lvl1_g, lvl1_b, eps12);       // BN+ReLU + fused scatter

    // node path: np1 raw + stats(slot1); np2 applies BN(slot1) on A-load, stats(slot2)
    k_nin<<<4096, 256>>>(nr, eps11);
    k_mma_p<false><<<dim3(GN, 2), 256, SMEM_BYTES>>>(p_nin, lvl2_w1, p_np1, NN, 128, 256,
                                p_sum + 256, p_sq + 256,
                                nullptr, nullptr, nullptr, nullptr, 0.f);
    k_mma_p<true><<<dim3(GN, 1), 256, SMEM_BYTES>>>(p_np1, lvl2_w2, p_np2, NN, 256, 128,
                                p_sum + 512, p_sq + 512,
                                p_sum + 256, p_sq + 256, lvl2_g1, lvl2_b1, 1.0f / NN);
    k_bnapply<<<4096, 256>>>(p_np2, out_node, NN, 127, p_sum + 512, p_sq + 512, lvl2_g2, lvl2_b2);

    // edge path: ein materialized (coalesced); ep1 raw + stats(slot3); ep2 BN-fused, stats(slot4)
    k_ein<<<2048, 128>>>(er, nr, eps2);
    k_mma_p<false><<<dim3(GTE, 2), 256, SMEM_BYTES>>>(p_ein, lift_w1, p_ep1, TE, 256, 256,
                                 p_sum + 768, p_sq + 768,
                                 nullptr, nullptr, nullptr, nullptr, 0.f);
    k_mma_p<true><<<dim3(GTE, 1), 256, SMEM_BYTES>>>(p_ep1, lift_w2, p_ep2, TE, 256, 128,
                                 p_sum + 1024, p_sq + 1024,
                                 p_sum + 768, p_sq + 768, lift_g1, lift_b1, 1.0f / TE);
    k_bnapply<<<8192, 256>>>(p_ep2, out_edge, TE, 127, p_sum + 1024, p_sq + 1024, lift_g2, lift_b2);
}